// round 8
// baseline (speedup 1.0000x reference)
#include <cuda_runtime.h>
#include <cuda_fp16.h>
#include <cstdint>

// Problem dims (fixed): enc_out [32,2048,1024] f32, dec_hidden [32,1024],
// Wa [1024,1024], Ua [1024,1024], Va [1024]. Output context [32,1024] f32.
#define BB 32
#define TT 2048
#define HH 1024
#define UU 1024
#define MM (BB * TT)   // 65536

// Scratch (no allocs allowed -> device globals)
__device__ float g_dproj[BB * UU];     // [32][1024]
__device__ float g_score[BB * TT];     // [32][2048], reused for alpha

// ---------------------------------------------------------------------------
// Helpers (base-sm_103-safe: mbarrier, mma.sync fp16)
// ---------------------------------------------------------------------------
__device__ __forceinline__ uint32_t smem_u32(const void* p) {
    uint32_t a;
    asm("{ .reg .u64 t; cvta.to.shared.u64 t, %1; cvt.u32.u64 %0, t; }"
        : "=r"(a) : "l"(p));
    return a;
}

#define MBAR_INIT(addr, cnt) \
    asm volatile("mbarrier.init.shared.b64 [%0], %1;" :: "r"(addr), "r"(cnt) : "memory")

// mbarrier.arrive has release.cta semantics: prior st.shared are visible to
// threads that acquire via try_wait on the same barrier.
#define MBAR_ARRIVE(addr) \
    asm volatile("mbarrier.arrive.shared.b64 _, [%0];" :: "r"(addr) : "memory")

#define MBAR_WAIT(addr, par) do {                                              \
    uint32_t _m = (addr), _p = (par), _d;                                      \
    asm volatile("{\n\t.reg .pred p;\n\t"                                      \
        "mbarrier.try_wait.parity.acquire.cta.shared::cta.b64 p, [%1], %2;\n\t" \
        "selp.b32 %0, 1, 0, p;\n\t}"                                           \
        : "=r"(_d) : "r"(_m), "r"(_p) : "memory");                             \
    if (!_d) {                                                                 \
        asm volatile("{\n\t.reg .pred P1;\n\t"                                 \
            "W_%=:\n\t"                                                        \
            "mbarrier.try_wait.parity.acquire.cta.shared::cta.b64 P1, [%0], %1, 0x989680;\n\t" \
            "@P1 bra.uni D_%=;\n\t"                                            \
            "bra.uni W_%=;\n\t"                                                \
            "D_%=:\n\t}" :: "r"(_m), "r"(_p) : "memory");                      \
    }                                                                          \
} while (0)

// fp16 mma m16n8k16, f32 accumulate. a: 4 regs (half2), b: 2 regs (half2).
__device__ __forceinline__ void mma_f16(float c[4], const uint32_t a[4],
                                        const uint32_t b[2]) {
    asm volatile(
        "mma.sync.aligned.m16n8k16.row.col.f32.f16.f16.f32 "
        "{%0,%1,%2,%3}, {%4,%5,%6,%7}, {%8,%9}, {%0,%1,%2,%3};\n"
        : "+f"(c[0]), "+f"(c[1]), "+f"(c[2]), "+f"(c[3])
        : "r"(a[0]), "r"(a[1]), "r"(a[2]), "r"(a[3]), "r"(b[0]), "r"(b[1]));
}

__device__ __forceinline__ float fast_tanh(float x) {
    float e, r;
    asm("ex2.approx.f32 %0, %1;" : "=f"(e) : "f"(x * 2.8853900817779268f));
    asm("rcp.approx.f32 %0, %1;" : "=f"(r) : "f"(e + 1.0f));
    return __fmaf_rn(-2.0f, r, 1.0f);
}

// ---------------------------------------------------------------------------
// Phase 0: zero scratch + output;  dummy: ncu launch-slot alignment
// ---------------------------------------------------------------------------
__global__ void init_kernel(float* out) {
    int i = blockIdx.x * blockDim.x + threadIdx.x;
    if (i < BB * UU) g_dproj[i] = 0.0f;
    if (i < BB * TT) g_score[i] = 0.0f;
    if (i < BB * HH) out[i] = 0.0f;
}
__global__ void dummy_kernel() {}

// ---------------------------------------------------------------------------
// Phase 1: dec_proj[b][u] = sum_h dec[b][h] * Wa[h][u]
// ---------------------------------------------------------------------------
__global__ void dproj_kernel(const float* __restrict__ dec,
                             const float* __restrict__ Wa) {
    const int tid = threadIdx.x;
    const int u   = blockIdx.x * 128 + tid;
    const int h0  = blockIdx.y * 256;
    const int b0  = blockIdx.z * 8;

    __shared__ float sdec[8][256];
    #pragma unroll
    for (int i = 0; i < 16; ++i) {
        int idx = i * 128 + tid;
        sdec[idx >> 8][idx & 255] = dec[(b0 + (idx >> 8)) * HH + h0 + (idx & 255)];
    }
    __syncthreads();

    float acc[8];
    #pragma unroll
    for (int j = 0; j < 8; ++j) acc[j] = 0.0f;
    #pragma unroll 4
    for (int h = 0; h < 256; ++h) {
        float wa = Wa[(size_t)(h0 + h) * UU + u];
        #pragma unroll
        for (int j = 0; j < 8; ++j) acc[j] += sdec[j][h] * wa;
    }
    #pragma unroll
    for (int j = 0; j < 8; ++j)
        atomicAdd(&g_dproj[(b0 + j) * UU + u], acc[j]);
}

// ---------------------------------------------------------------------------
// Phase 2: warp-specialized FP16 MMA GEMM, fused tanh + Va-reduce -> g_score
// Block tile 128(M) x 256(N), BK=16, 8-stage mbarrier ring, no __syncthreads
// in the mainloop. 320 threads: warps 0-7 consumers (2x4, 64x64 warp tile,
// m16n8k16 fp16), warps 8-9 producers (LDG f32 -> cvt fp16 -> STS).
// Stage layout (word = 4B = half2):
//   A: 128 rows x 8 words (k-pairs, lo=even k), pitch 12 words -> 6144 B.
//      Bank(reg0) = 12g + t over lanes -> all 32 banks distinct.
//   B: 8 pair-rows x 256 words ({k_even,k_odd} per word), pitch 264 words
//      -> 8448 B. Bank = 8t + g -> distinct.
// ---------------------------------------------------------------------------
#define NSTAGE 8
#define BK 16
#define APITCHW 12
#define BPITCHW 264
#define A_BYTES (128 * APITCHW * 4)                 // 6144
#define STAGE_BYTES (A_BYTES + 8 * BPITCHW * 4)     // 14592
#define SDP_OFF 128
#define SVA_OFF 1152
#define STAGE0 2176
#define GEMM_SMEM (STAGE0 + NSTAGE * STAGE_BYTES)   // 118912
#define NCHUNK (HH / BK)                             // 64

__global__ void __launch_bounds__(320, 1)
gemm_score_kernel(const float* __restrict__ enc, const float* __restrict__ Ua,
                  const float* __restrict__ Va) {
    extern __shared__ char smem[];
    const uint32_t sb = smem_u32(smem);
    const int tid = threadIdx.x;

    const int n0 = blockIdx.x * 256;
    const int m0 = blockIdx.y * 128;
    const int b  = m0 >> 11;

    if (tid == 0) {
        #pragma unroll
        for (int s = 0; s < NSTAGE; ++s) {
            MBAR_INIT(sb + s * 8, 64);         // full: 64 producer arrivals
            MBAR_INIT(sb + 64 + s * 8, 256);   // empty: 256 consumer arrivals
        }
    }
    if (tid < 256) {
        ((float*)(smem + SDP_OFF))[tid] = g_dproj[b * UU + n0 + tid];
        ((float*)(smem + SVA_OFF))[tid] = Va[n0 + tid];
    }
    __syncthreads();

    if (tid >= 256) {
        // ======================= producers (warps 8-9) =======================
        const int pt = tid - 256;  // 0..63
        // A task: idx = j*64+pt in 0..511: row = idx>>2, grp = idx&3
        //   loads f32[row][c*16 + 4grp .. +3] -> 2 half2 -> STS.64
        // B task: idx in 0..511: prow = idx>>6, nq = idx&63
        //   loads f32 rows k=c*16+2*prow, +1 at n0+4nq (float4 each)
        //   -> 4 half2 {ev,od} -> STS.128
        for (int c = 0; c < NCHUNK; ++c) {
            const int s = c & (NSTAGE - 1);
            if (c >= NSTAGE) MBAR_WAIT(sb + 64 + s * 8, ((c >> 3) - 1) & 1);
            const uint32_t st = sb + STAGE0 + s * STAGE_BYTES;
            const float* gA = enc + (size_t)m0 * HH + c * BK;
            const float* gB = Ua + (size_t)(c * BK) * UU + n0;

            float4 la[8], lev[8], lod[8];
            #pragma unroll
            for (int j = 0; j < 8; ++j) {
                int idx = j * 64 + pt;
                int row = idx >> 2, grp = idx & 3;
                la[j] = *(const float4*)(gA + (size_t)row * HH + grp * 4);
            }
            #pragma unroll
            for (int j = 0; j < 8; ++j) {
                int idx = j * 64 + pt;
                int prow = idx >> 6, nq = idx & 63;
                const float* p = gB + (size_t)(2 * prow) * UU + nq * 4;
                lev[j] = *(const float4*)p;
                lod[j] = *(const float4*)(p + UU);
            }
            #pragma unroll
            for (int j = 0; j < 8; ++j) {
                int idx = j * 64 + pt;
                int row = idx >> 2, grp = idx & 3;
                __half2 h0 = __floats2half2_rn(la[j].x, la[j].y);
                __half2 h1 = __floats2half2_rn(la[j].z, la[j].w);
                *(uint2*)(smem + STAGE0 + s * STAGE_BYTES
                          + row * (APITCHW * 4) + grp * 8) =
                    make_uint2(*(uint32_t*)&h0, *(uint32_t*)&h1);
            }
            #pragma unroll
            for (int j = 0; j < 8; ++j) {
                int idx = j * 64 + pt;
                int prow = idx >> 6, nq = idx & 63;
                __half2 p0 = __floats2half2_rn(lev[j].x, lod[j].x);
                __half2 p1 = __floats2half2_rn(lev[j].y, lod[j].y);
                __half2 p2 = __floats2half2_rn(lev[j].z, lod[j].z);
                __half2 p3 = __floats2half2_rn(lev[j].w, lod[j].w);
                *(uint4*)(smem + STAGE0 + s * STAGE_BYTES + A_BYTES
                          + prow * (BPITCHW * 4) + nq * 16) =
                    make_uint4(*(uint32_t*)&p0, *(uint32_t*)&p1,
                               *(uint32_t*)&p2, *(uint32_t*)&p3);
            }
            MBAR_ARRIVE(sb + s * 8);
        }
        return;
    }

    // ======================== consumers (warps 0-7) ==========================
    const int wid = tid >> 5, lane = tid & 31;
    const int wm = wid >> 2, wn = wid & 3;     // 2 x 4 warps
    const int g = lane >> 2, q = lane & 3;     // q = t (k-pair index)

    float acc[4][8][4];
    #pragma unroll
    for (int i = 0; i < 4; ++i)
        #pragma unroll
        for (int j = 0; j < 8; ++j)
            #pragma unroll
            for (int k = 0; k < 4; ++k) acc[i][j][k] = 0.0f;

    for (int c = 0; c < NCHUNK; ++c) {
        const int s = c & (NSTAGE - 1);
        MBAR_WAIT(sb + s * 8, (c >> 3) & 1);
        const uint32_t* As =
            (const uint32_t*)(smem + STAGE0 + s * STAGE_BYTES);
        const uint32_t* Bs =
            (const uint32_t*)(smem + STAGE0 + s * STAGE_BYTES + A_BYTES);

        // A frags: reg0 = row(g) word q; reg1 = row(g+8) word q;
        //          reg2 = row(g) word q+4; reg3 = row(g+8) word q+4
        uint32_t af[4][4];
        #pragma unroll
        for (int mt = 0; mt < 4; ++mt) {
            const int rb_ = wm * 64 + mt * 16;
            af[mt][0] = As[(rb_ + g) * APITCHW + q];
            af[mt][1] = As[(rb_ + g + 8) * APITCHW + q];
            af[mt][2] = As[(rb_ + g) * APITCHW + q + 4];
            af[mt][3] = As[(rb_ + g + 8) * APITCHW + q + 4];
        }
        // B frags: reg0 = pair-row q, col cb; reg1 = pair-row q+4, col cb
        uint32_t bf[8][2];
        #pragma unroll
        for (int nt = 0; nt < 8; ++nt) {
            const int cb = wn * 64 + nt * 8 + g;
            bf[nt][0] = Bs[q * BPITCHW + cb];
            bf[nt][1] = Bs[(q + 4) * BPITCHW + cb];
        }
        #pragma unroll
        for (int mt = 0; mt < 4; ++mt)
            #pragma unroll
            for (int nt = 0; nt < 8; ++nt)
                mma_f16(acc[mt][nt], af[mt], bf[nt]);

        MBAR_ARRIVE(sb + 64 + s * 8);
    }

    // fused epilogue: score[m] += sum_n tanh(acc + dproj[n]) * Va[n]
    const float* dp = (const float*)(smem + SDP_OFF);
    const float* va = (const float*)(smem + SVA_OFF);
    #pragma unroll
    for (int mt = 0; mt < 4; ++mt) {
        float rs[2] = {0.0f, 0.0f};
        #pragma unroll
        for (int nt = 0; nt < 8; ++nt) {
            const int nb = wn * 64 + nt * 8 + (q << 1);
            const float dp0 = dp[nb],     va0 = va[nb];
            const float dp1 = dp[nb + 1], va1 = va[nb + 1];
            rs[0] += fast_tanh(acc[mt][nt][0] + dp0) * va0
                   + fast_tanh(acc[mt][nt][1] + dp1) * va1;
            rs[1] += fast_tanh(acc[mt][nt][2] + dp0) * va0
                   + fast_tanh(acc[mt][nt][3] + dp1) * va1;
        }
        #pragma unroll
        for (int r = 0; r < 2; ++r) {
            float v = rs[r];
            v += __shfl_xor_sync(0xffffffffu, v, 1);
            v += __shfl_xor_sync(0xffffffffu, v, 2);
            if (q == 0)
                atomicAdd(&g_score[m0 + wm * 64 + mt * 16 + (r << 3) + g], v);
        }
    }
}

// ---------------------------------------------------------------------------
// Phase 3: softmax over T per batch (in-place on g_score)
// ---------------------------------------------------------------------------
__global__ void softmax_kernel() {
    const int bb = blockIdx.x, tid = threadIdx.x;
    __shared__ float red[256];
    float* s = g_score + bb * TT;

    float m = -1e30f;
    for (int t = tid; t < TT; t += 256) m = fmaxf(m, s[t]);
    red[tid] = m; __syncthreads();
    for (int o = 128; o > 0; o >>= 1) {
        if (tid < o) red[tid] = fmaxf(red[tid], red[tid + o]);
        __syncthreads();
    }
    m = red[0]; __syncthreads();

    float sum = 0.0f;
    for (int t = tid; t < TT; t += 256) {
        float e = __expf(s[t] - m);
        s[t] = e;
        sum += e;
    }
    red[tid] = sum; __syncthreads();
    for (int o = 128; o > 0; o >>= 1) {
        if (tid < o) red[tid] += red[tid + o];
        __syncthreads();
    }
    const float inv = 1.0f / red[0];
    for (int t = tid; t < TT; t += 256) s[t] *= inv;
}

// ---------------------------------------------------------------------------
// Phase 4: context[b][h] = sum_t alpha[b][t]*enc[b][t][h]; T split x4, atomics
// ---------------------------------------------------------------------------
__global__ void context_kernel(const float* __restrict__ enc,
                               float* __restrict__ out) {
    const int bb = blockIdx.y;
    const int ts = blockIdx.z * 512;
    const int h  = blockIdx.x * 256 + threadIdx.x;
    __shared__ float sal[512];
    sal[threadIdx.x]       = g_score[bb * TT + ts + threadIdx.x];
    sal[threadIdx.x + 256] = g_score[bb * TT + ts + threadIdx.x + 256];
    __syncthreads();

    const float* e = enc + (size_t)bb * TT * HH + (size_t)ts * HH + h;
    float acc = 0.0f;
    #pragma unroll 8
    for (int t = 0; t < 512; ++t) acc += sal[t] * e[(size_t)t * HH];
    atomicAdd(&out[bb * HH + h], acc);
}

// ---------------------------------------------------------------------------
extern "C" void kernel_launch(void* const* d_in, const int* in_sizes, int n_in,
                              void* d_out, int out_size) {
    const float* enc = (const float*)d_in[0];
    const float* dec = (const float*)d_in[1];
    const float* Wa  = (const float*)d_in[2];
    const float* Ua  = (const float*)d_in[3];
    const float* Va  = (const float*)d_in[4];
    float* out = (float*)d_out;

    cudaFuncSetAttribute(gemm_score_kernel,
                         cudaFuncAttributeMaxDynamicSharedMemorySize, GEMM_SMEM);

    init_kernel<<<64, 1024>>>(out);                       // in-call idx 0
    dproj_kernel<<<dim3(8, 4, 4), 128>>>(dec, Wa);        // idx 1
    dummy_kernel<<<1, 32>>>();                            // idx 2 (ncu align)
    gemm_score_kernel<<<dim3(UU / 256, MM / 128), 320, GEMM_SMEM>>>(enc, Ua, Va); // idx 3
    softmax_kernel<<<BB, 256>>>();                        // idx 4
    context_kernel<<<dim3(HH / 256, BB, TT / 512), 256>>>(enc, out); // idx 5
}

// round 12
// speedup vs baseline: 2.0439x; 2.0439x over previous
#include <cuda_runtime.h>
#include <cuda_fp16.h>
#include <cstdint>

// Problem dims (fixed): enc_out [32,2048,1024] f32, dec_hidden [32,1024],
// Wa [1024,1024], Ua [1024,1024], Va [1024]. Output context [32,1024] f32.
#define BB 32
#define TT 2048
#define HH 1024
#define UU 1024
#define MM (BB * TT)   // 65536

// Scratch (no allocs allowed -> device globals)
__device__ float g_dproj[BB * UU];              // [32][1024]
__device__ float g_score[BB * TT];              // [32][2048], reused for alpha
// fp16 copies (one-shot convert; GEMM + context consume these)
__device__ __align__(16) __half g_ea[(size_t)MM * HH];      // enc fp16, 128MB
__device__ __align__(16) uint32_t g_ub[(HH / 2) * UU];      // Ua k-paired half2

// ---------------------------------------------------------------------------
// Helpers
// ---------------------------------------------------------------------------
__device__ __forceinline__ uint32_t smem_u32(const void* p) {
    uint32_t a;
    asm("{ .reg .u64 t; cvta.to.shared.u64 t, %1; cvt.u32.u64 %0, t; }"
        : "=r"(a) : "l"(p));
    return a;
}

__device__ __forceinline__ void cp16(uint32_t saddr, const void* g) {
    asm volatile("cp.async.cg.shared.global [%0], [%1], 16;"
                 :: "r"(saddr), "l"(g) : "memory");
}

#define MBAR_INIT(addr, cnt) \
    asm volatile("mbarrier.init.shared.b64 [%0], %1;" :: "r"(addr), "r"(cnt) : "memory")

#define MBAR_ARRIVE(addr) \
    asm volatile("mbarrier.arrive.shared.b64 _, [%0];" :: "r"(addr) : "memory")

// .noinc is load-bearing (round-5 deadlock without it): the completed cp.async
// group is a plain arrival; 64 arrivals/phase == init count.
#define MBAR_ARRIVE_CP_NOINC(addr) \
    asm volatile("cp.async.mbarrier.arrive.noinc.shared::cta.b64 [%0];" :: "r"(addr) : "memory")

#define MBAR_WAIT(addr, par) do {                                              \
    uint32_t _m = (addr), _p = (par), _d;                                      \
    asm volatile("{\n\t.reg .pred p;\n\t"                                      \
        "mbarrier.try_wait.parity.acquire.cta.shared::cta.b64 p, [%1], %2;\n\t" \
        "selp.b32 %0, 1, 0, p;\n\t}"                                           \
        : "=r"(_d) : "r"(_m), "r"(_p) : "memory");                             \
    if (!_d) {                                                                 \
        asm volatile("{\n\t.reg .pred P1;\n\t"                                 \
            "W_%=:\n\t"                                                        \
            "mbarrier.try_wait.parity.acquire.cta.shared::cta.b64 P1, [%0], %1, 0x989680;\n\t" \
            "@P1 bra.uni D_%=;\n\t"                                            \
            "bra.uni W_%=;\n\t"                                                \
            "D_%=:\n\t}" :: "r"(_m), "r"(_p) : "memory");                      \
    }                                                                          \
} while (0)

__device__ __forceinline__ void mma_f16(float c[4], const uint32_t a[4],
                                        const uint32_t b[2]) {
    asm volatile(
        "mma.sync.aligned.m16n8k16.row.col.f32.f16.f16.f32 "
        "{%0,%1,%2,%3}, {%4,%5,%6,%7}, {%8,%9}, {%0,%1,%2,%3};\n"
        : "+f"(c[0]), "+f"(c[1]), "+f"(c[2]), "+f"(c[3])
        : "r"(a[0]), "r"(a[1]), "r"(a[2]), "r"(a[3]), "r"(b[0]), "r"(b[1]));
}

__device__ __forceinline__ float fast_tanh(float x) {
    float e, r;
    asm("ex2.approx.f32 %0, %1;" : "=f"(e) : "f"(x * 2.8853900817779268f));
    asm("rcp.approx.f32 %0, %1;" : "=f"(r) : "f"(e + 1.0f));
    return __fmaf_rn(-2.0f, r, 1.0f);
}

// ---------------------------------------------------------------------------
// Phase 0: zero scratch + output
// ---------------------------------------------------------------------------
__global__ void init_kernel(float* out) {
    int i = blockIdx.x * blockDim.x + threadIdx.x;
    if (i < BB * UU) g_dproj[i] = 0.0f;
    if (i < BB * TT) g_score[i] = 0.0f;
    if (i < BB * HH) out[i] = 0.0f;
}

// ---------------------------------------------------------------------------
// Phase 1: dec_proj[b][u] = sum_h dec[b][h] * Wa[h][u]
// ---------------------------------------------------------------------------
__global__ void dproj_kernel(const float* __restrict__ dec,
                             const float* __restrict__ Wa) {
    const int tid = threadIdx.x;
    const int u   = blockIdx.x * 128 + tid;
    const int h0  = blockIdx.y * 256;
    const int b0  = blockIdx.z * 8;

    __shared__ float sdec[8][256];
    #pragma unroll
    for (int i = 0; i < 16; ++i) {
        int idx = i * 128 + tid;
        sdec[idx >> 8][idx & 255] = dec[(b0 + (idx >> 8)) * HH + h0 + (idx & 255)];
    }
    __syncthreads();

    float acc[8];
    #pragma unroll
    for (int j = 0; j < 8; ++j) acc[j] = 0.0f;
    #pragma unroll 4
    for (int h = 0; h < 256; ++h) {
        float wa = Wa[(size_t)(h0 + h) * UU + u];
        #pragma unroll
        for (int j = 0; j < 8; ++j) acc[j] += sdec[j][h] * wa;
    }
    #pragma unroll
    for (int j = 0; j < 8; ++j)
        atomicAdd(&g_dproj[(b0 + j) * UU + u], acc[j]);
}

// ---------------------------------------------------------------------------
// Phase 1b: one-shot f32 -> fp16 convert.
//  enc: 8 floats/thread -> 8 halves (uint4 store), 8M units.
//  Ua:  k-paired: g_ub[kp*UU + n] = half2{Ua[2kp][n], Ua[2kp+1][n]}, 512K units.
// ---------------------------------------------------------------------------
#define ENC_UNITS ((size_t)MM * HH / 8)   // 8388608
#define UA_UNITS  ((HH / 2) * UU)         // 524288

__global__ void convert_kernel(const float* __restrict__ enc,
                               const float* __restrict__ Ua) {
    size_t i = (size_t)blockIdx.x * blockDim.x + threadIdx.x;
    if (i < ENC_UNITS) {
        const float4 f0 = *(const float4*)(enc + i * 8);
        const float4 f1 = *(const float4*)(enc + i * 8 + 4);
        __half2 h0 = __floats2half2_rn(f0.x, f0.y);
        __half2 h1 = __floats2half2_rn(f0.z, f0.w);
        __half2 h2 = __floats2half2_rn(f1.x, f1.y);
        __half2 h3 = __floats2half2_rn(f1.z, f1.w);
        *(uint4*)(g_ea + i * 8) = make_uint4(
            *(uint32_t*)&h0, *(uint32_t*)&h1, *(uint32_t*)&h2, *(uint32_t*)&h3);
    } else {
        size_t j = i - ENC_UNITS;
        if (j < UA_UNITS) {
            int kp = (int)(j >> 10), n = (int)(j & 1023);
            __half2 v = __floats2half2_rn(Ua[(size_t)(2 * kp) * UU + n],
                                          Ua[(size_t)(2 * kp + 1) * UU + n]);
            g_ub[kp * UU + n] = *(uint32_t*)&v;
        }
    }
}

// ---------------------------------------------------------------------------
// Phase 2: warp-specialized FP16 MMA GEMM, fused tanh + Va-reduce -> g_score
// Block tile 128(M) x 256(N), BK=16, 8-stage ring, no __syncthreads in the
// mainloop. 320 threads: warps 0-7 consumers (2x4, 64x64 warp tile,
// m16n8k16), warps 8-9 producers: pure cp.async from pre-converted fp16,
// 12 cp16/thread/chunk.
// Stage (word = 4B = half2):
//   A: 128 rows x 8 words (k-pairs), pitch 12 words (6144 B).
//   B: 8 pair-rows x 256 words, pitch 264 words (8448 B).
// ---------------------------------------------------------------------------
#define NSTAGE 8
#define BK 16
#define APITCHW 12
#define BPITCHW 264
#define A_BYTES (128 * APITCHW * 4)                 // 6144
#define STAGE_BYTES (A_BYTES + 8 * BPITCHW * 4)     // 14592
#define SDP_OFF 128
#define SVA_OFF 1152
#define STAGE0 2176
#define GEMM_SMEM (STAGE0 + NSTAGE * STAGE_BYTES)   // 118912
#define NCHUNK (HH / BK)                             // 64

__global__ void __launch_bounds__(320, 1)
gemm_score_kernel(const float* __restrict__ Va) {
    extern __shared__ char smem[];
    const uint32_t sb = smem_u32(smem);
    const int tid = threadIdx.x;

    const int n0 = blockIdx.x * 256;
    const int m0 = blockIdx.y * 128;
    const int b  = m0 >> 11;

    if (tid == 0) {
        #pragma unroll
        for (int s = 0; s < NSTAGE; ++s) {
            MBAR_INIT(sb + s * 8, 64);         // full: 64 producer cp-arrivals
            MBAR_INIT(sb + 64 + s * 8, 256);   // empty: 256 consumer arrivals
        }
    }
    if (tid < 256) {
        ((float*)(smem + SDP_OFF))[tid] = g_dproj[b * UU + n0 + tid];
        ((float*)(smem + SVA_OFF))[tid] = Va[n0 + tid];
    }
    __syncthreads();

    if (tid >= 256) {
        // ======================= producers (warps 8-9) =======================
        const int pt = tid - 256;  // 0..63
        for (int c = 0; c < NCHUNK; ++c) {
            const int s = c & (NSTAGE - 1);
            if (c >= NSTAGE) MBAR_WAIT(sb + 64 + s * 8, ((c >> 3) - 1) & 1);
            const uint32_t st = sb + STAGE0 + s * STAGE_BYTES;
            // A: 256 x 16B: idx -> row = idx>>1 (0..127), grp = idx&1
            const __half* gA = g_ea + (size_t)m0 * HH + c * BK;
            #pragma unroll
            for (int j = 0; j < 4; ++j) {
                int idx = j * 64 + pt;
                int row = idx >> 1, grp = idx & 1;
                cp16(st + row * (APITCHW * 4) + grp * 16,
                     gA + (size_t)row * HH + grp * 8);
            }
            // B: 512 x 16B: idx -> prow = idx>>6 (0..7), nq = idx&63
            const uint32_t* gB = g_ub + (size_t)(c * 8) * UU + n0;
            #pragma unroll
            for (int j = 0; j < 8; ++j) {
                int idx = j * 64 + pt;
                int prow = idx >> 6, nq = idx & 63;
                cp16(st + A_BYTES + prow * (BPITCHW * 4) + nq * 16,
                     gB + (size_t)prow * UU + nq * 4);
            }
            MBAR_ARRIVE_CP_NOINC(sb + s * 8);
        }
        return;
    }

    // ======================== consumers (warps 0-7) ==========================
    const int wid = tid >> 5, lane = tid & 31;
    const int wm = wid >> 2, wn = wid & 3;     // 2 x 4 warps
    const int g = lane >> 2, q = lane & 3;     // q = k-pair index

    float acc[4][8][4];
    #pragma unroll
    for (int i = 0; i < 4; ++i)
        #pragma unroll
        for (int j = 0; j < 8; ++j)
            #pragma unroll
            for (int k = 0; k < 4; ++k) acc[i][j][k] = 0.0f;

    for (int c = 0; c < NCHUNK; ++c) {
        const int s = c & (NSTAGE - 1);
        MBAR_WAIT(sb + s * 8, (c >> 3) & 1);
        const uint32_t* As =
            (const uint32_t*)(smem + STAGE0 + s * STAGE_BYTES);
        const uint32_t* Bs =
            (const uint32_t*)(smem + STAGE0 + s * STAGE_BYTES + A_BYTES);

        uint32_t af[4][4];
        #pragma unroll
        for (int mt = 0; mt < 4; ++mt) {
            const int rb_ = wm * 64 + mt * 16;
            af[mt][0] = As[(rb_ + g) * APITCHW + q];
            af[mt][1] = As[(rb_ + g + 8) * APITCHW + q];
            af[mt][2] = As[(rb_ + g) * APITCHW + q + 4];
            af[mt][3] = As[(rb_ + g + 8) * APITCHW + q + 4];
        }
        uint32_t bf[8][2];
        #pragma unroll
        for (int nt = 0; nt < 8; ++nt) {
            const int cb = wn * 64 + nt * 8 + g;
            bf[nt][0] = Bs[q * BPITCHW + cb];
            bf[nt][1] = Bs[(q + 4) * BPITCHW + cb];
        }
        #pragma unroll
        for (int mt = 0; mt < 4; ++mt)
            #pragma unroll
            for (int nt = 0; nt < 8; ++nt)
                mma_f16(acc[mt][nt], af[mt], bf[nt]);

        MBAR_ARRIVE(sb + 64 + s * 8);
    }

    // fused epilogue: score[m] += sum_n tanh(acc + dproj[n]) * Va[n]
    const float* dp = (const float*)(smem + SDP_OFF);
    const float* va = (const float*)(smem + SVA_OFF);
    #pragma unroll
    for (int mt = 0; mt < 4; ++mt) {
        float rs[2] = {0.0f, 0.0f};
        #pragma unroll
        for (int nt = 0; nt < 8; ++nt) {
            const int nb = wn * 64 + nt * 8 + (q << 1);
            const float dp0 = dp[nb],     va0 = va[nb];
            const float dp1 = dp[nb + 1], va1 = va[nb + 1];
            rs[0] += fast_tanh(acc[mt][nt][0] + dp0) * va0
                   + fast_tanh(acc[mt][nt][1] + dp1) * va1;
            rs[1] += fast_tanh(acc[mt][nt][2] + dp0) * va0
                   + fast_tanh(acc[mt][nt][3] + dp1) * va1;
        }
        #pragma unroll
        for (int r = 0; r < 2; ++r) {
            float v = rs[r];
            v += __shfl_xor_sync(0xffffffffu, v, 1);
            v += __shfl_xor_sync(0xffffffffu, v, 2);
            if (q == 0)
                atomicAdd(&g_score[m0 + wm * 64 + mt * 16 + (r << 3) + g], v);
        }
    }
}

// ---------------------------------------------------------------------------
// Phase 3: softmax over T per batch (in-place on g_score)
// ---------------------------------------------------------------------------
__global__ void softmax_kernel() {
    const int bb = blockIdx.x, tid = threadIdx.x;
    __shared__ float red[256];
    float* s = g_score + bb * TT;

    float m = -1e30f;
    for (int t = tid; t < TT; t += 256) m = fmaxf(m, s[t]);
    red[tid] = m; __syncthreads();
    for (int o = 128; o > 0; o >>= 1) {
        if (tid < o) red[tid] = fmaxf(red[tid], red[tid + o]);
        __syncthreads();
    }
    m = red[0]; __syncthreads();

    float sum = 0.0f;
    for (int t = tid; t < TT; t += 256) {
        float e = __expf(s[t] - m);
        s[t] = e;
        sum += e;
    }
    red[tid] = sum; __syncthreads();
    for (int o = 128; o > 0; o >>= 1) {
        if (tid < o) red[tid] += red[tid + o];
        __syncthreads();
    }
    const float inv = 1.0f / red[0];
    for (int t = tid; t < TT; t += 256) s[t] *= inv;
}

// ---------------------------------------------------------------------------
// Phase 4: context[b][h] = sum_t alpha[b][t]*enc[b][t][h]; reads fp16 enc
// copy (half the DRAM traffic). Grid x: HH/512 = 2 blocks x 256 threads
// -> h2 in [0, 512) exactly (round-11 OOB fixed). T split x4 with atomics.
// ---------------------------------------------------------------------------
__global__ void context_kernel(float* __restrict__ out) {
    const int bb = blockIdx.y;
    const int ts = blockIdx.z * 512;
    const int h2 = blockIdx.x * 256 + threadIdx.x;  // 0..511 (half2 column)
    __shared__ float sal[512];
    sal[threadIdx.x]       = g_score[bb * TT + ts + threadIdx.x];
    sal[threadIdx.x + 256] = g_score[bb * TT + ts + threadIdx.x + 256];
    __syncthreads();

    const __half2* e = (const __half2*)(g_ea + (size_t)bb * TT * HH
                                        + (size_t)ts * HH) + h2;
    float a0 = 0.0f, a1 = 0.0f;
    #pragma unroll 8
    for (int t = 0; t < 512; ++t) {
        float2 v = __half22float2(e[(size_t)t * (HH / 2)]);
        a0 += sal[t] * v.x;
        a1 += sal[t] * v.y;
    }
    atomicAdd(&out[bb * HH + h2 * 2], a0);
    atomicAdd(&out[bb * HH + h2 * 2 + 1], a1);
}

// ---------------------------------------------------------------------------
extern "C" void kernel_launch(void* const* d_in, const int* in_sizes, int n_in,
                              void* d_out, int out_size) {
    const float* enc = (const float*)d_in[0];
    const float* dec = (const float*)d_in[1];
    const float* Wa  = (const float*)d_in[2];
    const float* Ua  = (const float*)d_in[3];
    const float* Va  = (const float*)d_in[4];
    float* out = (float*)d_out;

    cudaFuncSetAttribute(gemm_score_kernel,
                         cudaFuncAttributeMaxDynamicSharedMemorySize, GEMM_SMEM);

    const int cvt_blocks = (int)((ENC_UNITS + UA_UNITS + 255) / 256);
    init_kernel<<<64, 1024>>>(out);                       // idx 0
    dproj_kernel<<<dim3(8, 4, 4), 128>>>(dec, Wa);        // idx 1
    convert_kernel<<<cvt_blocks, 256>>>(enc, Ua);         // idx 2
    gemm_score_kernel<<<dim3(UU / 256, MM / 128), 320, GEMM_SMEM>>>(Va); // idx 3
    softmax_kernel<<<BB, 256>>>();                        // idx 4
    context_kernel<<<dim3(HH / 512, BB, TT / 512), 256>>>(out); // idx 5
}